// round 6
// baseline (speedup 1.0000x reference)
#include <cuda_runtime.h>

// GEMV: out[1, 8192] = x[1, 8192] @ W[8192, 8192] + b
// d_in[0]=x (8192 f32), d_in[1]=W (8192x8192 f32 row-major), d_in[2]=b (8192 f32).
//
// R4: DRAM=77.8% with occ=39.5% -> MLP-starved (14KB in flight/SM vs 25KB
// needed by Little's law at 577cyc DRAM latency). Double the grid via
// ROWS_PER_SPLIT 128->64 (2048 blocks, ~55 warps/SM) to double in-flight
// bytes. W loads use __ldcs (read-once, evict-first).

static constexpr int IN_LEN  = 8192;
static constexpr int OUT_LEN = 8192;

static constexpr int THREADS        = 128;
static constexpr int COLS_PER_BLOCK = THREADS * 4;               // 512
static constexpr int COL_BLOCKS     = OUT_LEN / COLS_PER_BLOCK;  // 16
static constexpr int ROWS_PER_SPLIT = 64;
static constexpr int ROW_SPLITS     = IN_LEN / ROWS_PER_SPLIT;   // 128
// grid = 16 x 128 = 2048 blocks -> ~13.8 CTAs/SM, ~55 warps/SM.

__global__ void dense_init_bias(const float* __restrict__ b,
                                float* __restrict__ out) {
    int j = blockIdx.x * blockDim.x + threadIdx.x;
    if (j < OUT_LEN) out[j] = b[j];
}

__global__ __launch_bounds__(THREADS, 12)
void dense_gemv_splitk(const float* __restrict__ x,
                       const float* __restrict__ W,
                       float* __restrict__ out) {
    const int col0 = blockIdx.x * COLS_PER_BLOCK + threadIdx.x * 4;
    const int row0 = blockIdx.y * ROWS_PER_SPLIT;

    __shared__ float xs[ROWS_PER_SPLIT];
    if (threadIdx.x < ROWS_PER_SPLIT) xs[threadIdx.x] = x[row0 + threadIdx.x];
    __syncthreads();

    const float4* __restrict__ Wp =
        reinterpret_cast<const float4*>(W + (size_t)row0 * OUT_LEN + col0);
    const size_t row_stride_v4 = OUT_LEN / 4;

    float4 acc = make_float4(0.f, 0.f, 0.f, 0.f);

    // 8 independent streaming float4 loads per unroll body; W is read
    // exactly once -> evict-first keeps L2 clean.
    #pragma unroll 8
    for (int i = 0; i < ROWS_PER_SPLIT; i++) {
        const float xv = xs[i];
        const float4 w = __ldcs(&Wp[(size_t)i * row_stride_v4]);
        acc.x = fmaf(xv, w.x, acc.x);
        acc.y = fmaf(xv, w.y, acc.y);
        acc.z = fmaf(xv, w.z, acc.z);
        acc.w = fmaf(xv, w.w, acc.w);
    }

    // Split-K combine: 128 atomics per output address over the whole kernel,
    // spread across 8192 addresses -> hidden under the HBM stream.
    atomicAdd(&out[col0 + 0], acc.x);
    atomicAdd(&out[col0 + 1], acc.y);
    atomicAdd(&out[col0 + 2], acc.z);
    atomicAdd(&out[col0 + 3], acc.w);
}

extern "C" void kernel_launch(void* const* d_in, const int* in_sizes, int n_in,
                              void* d_out, int out_size) {
    const float* x = (const float*)d_in[0];
    const float* W = (const float*)d_in[1];
    const float* b = (const float*)d_in[2];
    float* out = (float*)d_out;

    dense_init_bias<<<OUT_LEN / 256, 256>>>(b, out);

    dim3 grid(COL_BLOCKS, ROW_SPLITS);
    dense_gemv_splitk<<<grid, THREADS>>>(x, W, out);
}

// round 7
// speedup vs baseline: 1.0994x; 1.0994x over previous
#include <cuda_runtime.h>

// GEMV: out[1, 8192] = x[1, 8192] @ W[8192, 8192] + b
// d_in[0]=x (8192 f32), d_in[1]=W (8192x8192 f32 row-major), d_in[2]=b.
//
// R6: back to the single-wave R4 geometry (1024 blocks = 16 col-tiles x 64
// row-splits, ~6.9 CTAs/SM; R5's 2048-block config hit a 2-wave tail and
// regressed). MLP now comes from per-thread depth: unroll 16 with a 7-CTA
// launch bound (~73-reg budget) so ptxas can front-batch 12-16 LDG.128 per
// thread. Bias folded into blockIdx.y==0 accumulators over a memset-zeroed
// output (graph memset node replaces the init kernel).

static constexpr int IN_LEN  = 8192;
static constexpr int OUT_LEN = 8192;

static constexpr int THREADS        = 128;
static constexpr int COLS_PER_BLOCK = THREADS * 4;               // 512
static constexpr int COL_BLOCKS     = OUT_LEN / COLS_PER_BLOCK;  // 16
static constexpr int ROWS_PER_SPLIT = 128;
static constexpr int ROW_SPLITS     = IN_LEN / ROWS_PER_SPLIT;   // 64
// grid = 16 x 64 = 1024 blocks -> single wave at >=7 CTAs/SM.

__global__ __launch_bounds__(THREADS, 7)
void dense_gemv_splitk(const float* __restrict__ x,
                       const float* __restrict__ W,
                       const float* __restrict__ b,
                       float* __restrict__ out) {
    const int col0 = blockIdx.x * COLS_PER_BLOCK + threadIdx.x * 4;
    const int row0 = blockIdx.y * ROWS_PER_SPLIT;

    __shared__ float xs[ROWS_PER_SPLIT];
    xs[threadIdx.x] = x[row0 + threadIdx.x];
    __syncthreads();

    const float4* __restrict__ Wp =
        reinterpret_cast<const float4*>(W + (size_t)row0 * OUT_LEN + col0);
    const size_t row_stride_v4 = OUT_LEN / 4;

    float4 acc;
    if (blockIdx.y == 0) {
        // Fold bias into this split's partial (out starts zeroed).
        acc = *reinterpret_cast<const float4*>(b + col0);
    } else {
        acc = make_float4(0.f, 0.f, 0.f, 0.f);
    }

    // Deep unroll: 16 independent float4 LDGs per body; with the 7-CTA
    // register budget (~73 regs) ptxas can keep 12-16 in flight per thread.
    #pragma unroll 16
    for (int i = 0; i < ROWS_PER_SPLIT; i++) {
        const float xv = xs[i];
        const float4 w = Wp[(size_t)i * row_stride_v4];
        acc.x = fmaf(xv, w.x, acc.x);
        acc.y = fmaf(xv, w.y, acc.y);
        acc.z = fmaf(xv, w.z, acc.z);
        acc.w = fmaf(xv, w.w, acc.w);
    }

    // 64 atomics per output address over the kernel, spread across 8192
    // addresses -> hidden under the HBM stream.
    atomicAdd(&out[col0 + 0], acc.x);
    atomicAdd(&out[col0 + 1], acc.y);
    atomicAdd(&out[col0 + 2], acc.z);
    atomicAdd(&out[col0 + 3], acc.w);
}

extern "C" void kernel_launch(void* const* d_in, const int* in_sizes, int n_in,
                              void* d_out, int out_size) {
    const float* x = (const float*)d_in[0];
    const float* W = (const float*)d_in[1];
    const float* b = (const float*)d_in[2];
    float* out = (float*)d_out;

    // Zero the output (graph memset node); bias is added by the y==0 blocks.
    cudaMemsetAsync(out, 0, OUT_LEN * sizeof(float));

    dim3 grid(COL_BLOCKS, ROW_SPLITS);
    dense_gemv_splitk<<<grid, THREADS>>>(x, W, b, out);
}